// round 2
// baseline (speedup 1.0000x reference)
#include <cuda_runtime.h>
#include <cuda_bf16.h>
#include <stdint.h>

#define SEQ   256
#define BATCH 32
#define NIN   1024
#define NH    1024
#define NOUT  32000
#define G4    (4*NH)            // 4096
#define MROWS (SEQ*BATCH)       // 8192
#define LOGP_ELEMS (262144000LL)

// ---------------- static scratch (no allocations allowed) ----------------
__device__ __align__(16) __nv_bfloat16 g_Wlb  [(size_t)NOUT*NH];
__device__ __align__(16) float         g_G0   [(size_t)MROWS*G4];
__device__ __align__(16) float         g_G1   [(size_t)MROWS*G4];
__device__ __align__(16) float         g_ha   [(size_t)MROWS*NH];   // layer0 h, fp32
__device__ __align__(16) float         g_hb   [(size_t)MROWS*NH];   // layer1 h, fp32
__device__ __align__(16) __nv_bfloat16 g_hbb  [MROWS*NH];           // layer1 h, bf16 (head GEMM)
__device__ unsigned g_bar[2];

// ---------------- PTX helpers ----------------
__device__ __forceinline__ uint32_t smem_u32(const void* p) {
    return (uint32_t)__cvta_generic_to_shared(p);
}
__device__ __forceinline__ void ldm_x4(uint32_t (&r)[4], const void* p) {
    asm volatile("ldmatrix.sync.aligned.m8n8.x4.shared.b16 {%0,%1,%2,%3},[%4];"
        : "=r"(r[0]), "=r"(r[1]), "=r"(r[2]), "=r"(r[3]) : "r"(smem_u32(p)) : "memory");
}
__device__ __forceinline__ void ldm_x2(uint32_t (&r)[2], const void* p) {
    asm volatile("ldmatrix.sync.aligned.m8n8.x2.shared.b16 {%0,%1},[%2];"
        : "=r"(r[0]), "=r"(r[1]) : "r"(smem_u32(p)) : "memory");
}
__device__ __forceinline__ void mma16816(float (&d)[4], const uint32_t (&a)[4], const uint32_t (&b)[2]) {
    asm volatile("mma.sync.aligned.m16n8k16.row.col.f32.bf16.bf16.f32 "
                 "{%0,%1,%2,%3},{%4,%5,%6,%7},{%8,%9},{%0,%1,%2,%3};"
        : "+f"(d[0]), "+f"(d[1]), "+f"(d[2]), "+f"(d[3])
        : "r"(a[0]), "r"(a[1]), "r"(a[2]), "r"(a[3]), "r"(b[0]), "r"(b[1]));
}
__device__ __forceinline__ void mma_tf32(float (&d)[4], const uint32_t (&a)[4], const uint32_t (&b)[2]) {
    asm volatile("mma.sync.aligned.m16n8k8.row.col.f32.tf32.tf32.f32 "
                 "{%0,%1,%2,%3},{%4,%5,%6,%7},{%8,%9},{%0,%1,%2,%3};"
        : "+f"(d[0]), "+f"(d[1]), "+f"(d[2]), "+f"(d[3])
        : "r"(a[0]), "r"(a[1]), "r"(a[2]), "r"(a[3]), "r"(b[0]), "r"(b[1]));
}
__device__ __forceinline__ void cp16(void* s, const void* g) {
    asm volatile("cp.async.cg.shared.global [%0],[%1],16;"
        :: "r"(smem_u32(s)), "l"(g) : "memory");
}

// ---------------- convert fp32 -> bf16 ----------------
__global__ void f2bf_kernel(const float* __restrict__ s, __nv_bfloat16* __restrict__ d, int n) {
    int i = blockIdx.x * blockDim.x + threadIdx.x;
    int stride = gridDim.x * blockDim.x;
    for (; i < n; i += stride) d[i] = __float2bfloat16(s[i]);
}

// =================================================================
// bf16 GEMM (head): C[M,N] = A[M,K] @ B[N,K]^T + bias1
// BM=128 BN=128 BK=32, 256 threads, double-buffered cp.async.
// =================================================================
__device__ __forceinline__ void gemm_load_tiles(
    const __nv_bfloat16* __restrict__ A, const __nv_bfloat16* __restrict__ Bw,
    int K, int m0, int n0, int k0,
    __nv_bfloat16 (*sA)[40], __nv_bfloat16 (*sB)[40], int tid)
{
#pragma unroll
    for (int r = 0; r < 2; r++) {
        int ch  = tid + r * 256;
        int row = ch >> 2, c4 = ch & 3;
        cp16(&sA[row][c4 * 8], A + (size_t)(m0 + row) * K + (k0 + c4 * 8));
        cp16(&sB[row][c4 * 8], Bw + (size_t)(n0 + row) * K + (k0 + c4 * 8));
    }
    asm volatile("cp.async.commit_group;" ::: "memory");
}

__global__ __launch_bounds__(256) void gemm_kernel(
    const __nv_bfloat16* __restrict__ A, const __nv_bfloat16* __restrict__ Bw,
    const float* __restrict__ bias1,
    float* __restrict__ C, int M, int N, int K)
{
    __shared__ __nv_bfloat16 sA[2][128][40];
    __shared__ __nv_bfloat16 sB[2][128][40];
    const int tid = threadIdx.x;
    const int m0 = blockIdx.y * 128, n0 = blockIdx.x * 128;
    const int warp = tid >> 5, lane = tid & 31;
    const int mb = (warp & 1) * 64, nb = (warp >> 1) * 32;
    const int arow = lane & 15,   ak = (lane >> 4) * 8;
    const int brow = lane & 7,    bk = ((lane >> 3) & 1) * 8;

    float acc[4][4][4];
#pragma unroll
    for (int i = 0; i < 4; i++)
#pragma unroll
        for (int j = 0; j < 4; j++)
#pragma unroll
            for (int v = 0; v < 4; v++) acc[i][j][v] = 0.f;

    gemm_load_tiles(A, Bw, K, m0, n0, 0, sA[0], sB[0], tid);
    const int nk = K / 32;
    for (int it = 0; it < nk; ++it) {
        if (it + 1 < nk) {
            gemm_load_tiles(A, Bw, K, m0, n0, (it + 1) * 32, sA[(it + 1) & 1], sB[(it + 1) & 1], tid);
            asm volatile("cp.async.wait_group 1;" ::: "memory");
        } else {
            asm volatile("cp.async.wait_group 0;" ::: "memory");
        }
        __syncthreads();
        const int st = it & 1;
#pragma unroll
        for (int kk = 0; kk < 32; kk += 16) {
            uint32_t af[4][4]; uint32_t bfr[4][2];
#pragma unroll
            for (int mt = 0; mt < 4; mt++) ldm_x4(af[mt], &sA[st][mb + mt * 16 + arow][kk + ak]);
#pragma unroll
            for (int nt = 0; nt < 4; nt++) ldm_x2(bfr[nt], &sB[st][nb + nt * 8 + brow][kk + bk]);
#pragma unroll
            for (int mt = 0; mt < 4; mt++)
#pragma unroll
                for (int nt = 0; nt < 4; nt++) mma16816(acc[mt][nt], af[mt], bfr[nt]);
        }
        __syncthreads();
    }

    const int g = lane >> 2, tt = lane & 3;
#pragma unroll
    for (int mt = 0; mt < 4; mt++) {
        const int r0 = m0 + mb + mt * 16 + g;
#pragma unroll
        for (int nt = 0; nt < 4; nt++) {
            const int col = n0 + nb + nt * 8 + 2 * tt;
            float b0 = bias1 ? bias1[col] : 0.f;
            float b1 = bias1 ? bias1[col + 1] : 0.f;
            float2* p0 = (float2*)(C + (size_t)r0 * N + col);
            float2* p1 = (float2*)(C + (size_t)(r0 + 8) * N + col);
            *p0 = make_float2(acc[mt][nt][0] + b0, acc[mt][nt][1] + b1);
            *p1 = make_float2(acc[mt][nt][2] + b0, acc[mt][nt][3] + b1);
        }
    }
}

// =================================================================
// tf32 GEMM (gate pre-GEMMs): C[M,N] = A[M,K] @ B[N,K]^T + b1 + b2
// fp32 in/out (HW truncates operands to tf32). BM=128 BN=64 BK=32.
// =================================================================
#define G32_SA (2*128*36)
#define G32_SB (2*64*36)
#define SMEM_G32 ((G32_SA + G32_SB)*4)

__device__ __forceinline__ void g32_load(
    const float* __restrict__ A, const float* __restrict__ Bw,
    int K, int m0, int n0, int k0, float* sA, float* sB, int tid)
{
#pragma unroll
    for (int r = 0; r < 4; r++) {
        int idx = tid + r * 256;
        int row = idx >> 3, ch = idx & 7;
        cp16(sA + row * 36 + ch * 4, A + (size_t)(m0 + row) * K + k0 + ch * 4);
    }
#pragma unroll
    for (int r = 0; r < 2; r++) {
        int idx = tid + r * 256;
        int row = idx >> 3, ch = idx & 7;
        cp16(sB + row * 36 + ch * 4, Bw + (size_t)(n0 + row) * K + k0 + ch * 4);
    }
    asm volatile("cp.async.commit_group;" ::: "memory");
}

__global__ __launch_bounds__(256) void gemm32_kernel(
    const float* __restrict__ A, const float* __restrict__ Bw,
    const float* __restrict__ bias1, const float* __restrict__ bias2,
    float* __restrict__ C, int M, int N, int K)
{
    extern __shared__ float sm32[];
    float* sAb = sm32;                // [2][128][36]
    float* sBb = sm32 + G32_SA;       // [2][64][36]

    const int tid = threadIdx.x;
    const int m0 = blockIdx.y * 128, n0 = blockIdx.x * 64;
    const int warp = tid >> 5, lane = tid & 31;
    const int mb = (warp & 3) * 32, nb = (warp >> 2) * 32;
    const int arow = lane & 15,  ak4 = (lane >> 4) * 4;
    const int brow = lane & 7,   bk4 = ((lane >> 3) & 1) * 4;

    float acc[2][4][4];
#pragma unroll
    for (int i = 0; i < 2; i++)
#pragma unroll
        for (int j = 0; j < 4; j++)
#pragma unroll
            for (int v = 0; v < 4; v++) acc[i][j][v] = 0.f;

    g32_load(A, Bw, K, m0, n0, 0, sAb, sBb, tid);
    const int nk = K / 32;
    for (int it = 0; it < nk; ++it) {
        if (it + 1 < nk) {
            g32_load(A, Bw, K, m0, n0, (it + 1) * 32,
                     sAb + ((it + 1) & 1) * 128 * 36, sBb + ((it + 1) & 1) * 64 * 36, tid);
            asm volatile("cp.async.wait_group 1;" ::: "memory");
        } else {
            asm volatile("cp.async.wait_group 0;" ::: "memory");
        }
        __syncthreads();
        const float* sAs = sAb + (it & 1) * 128 * 36;
        const float* sBs = sBb + (it & 1) * 64 * 36;
#pragma unroll
        for (int ks = 0; ks < 4; ks++) {
            uint32_t af[2][4]; uint32_t bfr[4][2];
#pragma unroll
            for (int mt = 0; mt < 2; mt++)
                ldm_x4(af[mt], sAs + (mb + mt * 16 + arow) * 36 + ks * 8 + ak4);
#pragma unroll
            for (int nt = 0; nt < 4; nt++)
                ldm_x2(bfr[nt], sBs + (nb + nt * 8 + brow) * 36 + ks * 8 + bk4);
#pragma unroll
            for (int mt = 0; mt < 2; mt++)
#pragma unroll
                for (int nt = 0; nt < 4; nt++) mma_tf32(acc[mt][nt], af[mt], bfr[nt]);
        }
        __syncthreads();
    }

    const int g = lane >> 2, tt = lane & 3;
#pragma unroll
    for (int mt = 0; mt < 2; mt++) {
        const int r0 = m0 + mb + mt * 16 + g;
#pragma unroll
        for (int nt = 0; nt < 4; nt++) {
            const int col = n0 + nb + nt * 8 + 2 * tt;
            float b0 = 0.f, b1 = 0.f;
            if (bias1) { b0 += bias1[col]; b1 += bias1[col + 1]; }
            if (bias2) { b0 += bias2[col]; b1 += bias2[col + 1]; }
            float2* p0 = (float2*)(C + (size_t)r0 * N + col);
            float2* p1 = (float2*)(C + (size_t)(r0 + 8) * N + col);
            *p0 = make_float2(acc[mt][nt][0] + b0, acc[mt][nt][1] + b1);
            *p1 = make_float2(acc[mt][nt][2] + b0, acc[mt][nt][3] + b1);
        }
    }
}

// =================================================================
// persistent single-layer LSTM recurrence (tf32)
// 128 CTAs x 256 threads. CTA owns 8 h-cols -> 32 gate rows (f32 in SMEM,
// 129KB resident). h(t-1) fp32 streamed from gmem in K-chunks of 128 via
// double-buffered cp.async. Gates via mma.tf32; activation fp32.
// =================================================================
#define W_STRIDE 1028
#define H_STRIDE 132
#define SMEM_LSTM ((32*W_STRIDE + 2*32*H_STRIDE + 32*36)*4)

__global__ __launch_bounds__(256) void lstm_pass(
    const float* __restrict__ Whh, const float* __restrict__ Gx,
    const float* __restrict__ h0, const float* __restrict__ c0,
    float* __restrict__ h_all, __nv_bfloat16* __restrict__ h_bf,
    float* __restrict__ hfin, float* __restrict__ cfin,
    unsigned* __restrict__ bar)
{
    extern __shared__ float smf[];
    float* Wf   = smf;                       // [32][W_STRIDE]
    float* Hs   = smf + 32 * W_STRIDE;       // [2][32][H_STRIDE]
    float* gbuf = Hs + 2 * 32 * H_STRIDE;    // [32][36]

    const int tid = threadIdx.x, warp = tid >> 5, lane = tid & 31;
    const int jbase = blockIdx.x * 8;
    const unsigned nblocks = gridDim.x;

    // resident weight slice (fp32): smem row r=q*8+jj  <-  Whh row q*NH + jbase + jj
#pragma unroll
    for (int i = 0; i < 32; i++) {
        int idx = tid + i * 256;
        int row = idx >> 8, ch = idx & 255;
        int grow = (row >> 3) * NH + jbase + (row & 7);
        *(float4*)(Wf + row * W_STRIDE + ch * 4) =
            *(const float4*)(Whh + (size_t)grow * NH + ch * 4);
    }

    const int b_act = tid >> 3, jj_act = tid & 7, col_act = jbase + jj_act;
    float c_st = c0[b_act * NH + col_act];

    const int mrow = (warp & 1) * 16, n0 = (warp >> 1) * 8;
    const int arow = lane & 15, ak4 = (lane >> 4) * 4;
    const int brow = lane & 7,  bk4 = ((lane >> 3) & 1) * 4;

    __syncthreads();

    for (int t = 0; t < SEQ; t++) {
        const float* hprev = (t == 0) ? h0 : (h_all + (size_t)(t - 1) * BATCH * NH);

        // issue chunk 0
#pragma unroll
        for (int r = 0; r < 4; r++) {
            int idx = tid + r * 256;
            int row = idx >> 5, ch = idx & 31;
            cp16(Hs + row * H_STRIDE + ch * 4, hprev + row * NH + ch * 4);
        }
        asm volatile("cp.async.commit_group;" ::: "memory");

        float acc[4] = {0.f, 0.f, 0.f, 0.f};
#pragma unroll 1
        for (int c = 0; c < 8; c++) {
            if (c < 7) {
                float* dst = Hs + ((c + 1) & 1) * 32 * H_STRIDE;
#pragma unroll
                for (int r = 0; r < 4; r++) {
                    int idx = tid + r * 256;
                    int row = idx >> 5, ch = idx & 31;
                    cp16(dst + row * H_STRIDE + ch * 4,
                         hprev + row * NH + (c + 1) * 128 + ch * 4);
                }
                asm volatile("cp.async.commit_group;" ::: "memory");
                asm volatile("cp.async.wait_group 1;" ::: "memory");
            } else {
                asm volatile("cp.async.wait_group 0;" ::: "memory");
            }
            __syncthreads();
            const float* hsb = Hs + (c & 1) * 32 * H_STRIDE;
            const float* wb  = Wf + c * 128;
#pragma unroll
            for (int ks = 0; ks < 16; ks++) {
                uint32_t af[4], bfr[2];
                ldm_x4(af,  hsb + (mrow + arow) * H_STRIDE + ks * 8 + ak4);
                ldm_x2(bfr, wb + (n0 + brow) * W_STRIDE + ks * 8 + bk4);
                mma_tf32(acc, af, bfr);
            }
            __syncthreads();
        }

        {
            int g = lane >> 2, tt = lane & 3;
            gbuf[(mrow + g) * 36 + n0 + 2 * tt]         = acc[0];
            gbuf[(mrow + g) * 36 + n0 + 2 * tt + 1]     = acc[1];
            gbuf[(mrow + g + 8) * 36 + n0 + 2 * tt]     = acc[2];
            gbuf[(mrow + g + 8) * 36 + n0 + 2 * tt + 1] = acc[3];
        }
        __syncthreads();

        // activation: thread (b, jj) handles one h column
        {
            const float* gx = Gx + ((size_t)t * BATCH + b_act) * G4 + col_act;
            float gi = gbuf[b_act * 36 + jj_act]      + gx[0];
            float gf = gbuf[b_act * 36 + 8 + jj_act]  + gx[NH];
            float gg = gbuf[b_act * 36 + 16 + jj_act] + gx[2 * NH];
            float go = gbuf[b_act * 36 + 24 + jj_act] + gx[3 * NH];
            float i_ = 1.f / (1.f + __expf(-gi));
            float f_ = 1.f / (1.f + __expf(-gf));
            float o_ = 1.f / (1.f + __expf(-go));
            float g_ = tanhf(gg);
            c_st = f_ * c_st + i_ * g_;
            float h_ = o_ * tanhf(c_st);
            size_t oidx = ((size_t)t * BATCH + b_act) * NH + col_act;
            h_all[oidx] = h_;
            if (h_bf) h_bf[oidx] = __float2bfloat16(h_);
            if (t == SEQ - 1) {
                hfin[b_act * NH + col_act] = h_;
                cfin[b_act * NH + col_act] = c_st;
            }
        }
        __syncthreads();

        // grid barrier (monotonic counter, reset before launch by memset)
        if (tid == 0) {
            __threadfence();
            atomicAdd(bar, 1u);
            unsigned target = (unsigned)(t + 1) * nblocks;
            unsigned v;
            do {
                asm volatile("ld.acquire.gpu.u32 %0,[%1];" : "=r"(v) : "l"(bar) : "memory");
            } while (v < target);
        }
        __syncthreads();
    }
}

// ---------------- in-place log-softmax over rows of 32000 ----------------
__global__ __launch_bounds__(256) void logsoftmax_kernel(float* __restrict__ logits) {
    float* p = logits + (size_t)blockIdx.x * NOUT;
    float m = -1e30f, s = 0.f;
    for (int j = threadIdx.x; j < NOUT; j += 256) {
        float x = p[j];
        if (x > m) { s = s * __expf(m - x) + 1.f; m = x; }
        else       { s += __expf(x - m); }
    }
    __shared__ float sm[256], ss[256];
    sm[threadIdx.x] = m; ss[threadIdx.x] = s;
    __syncthreads();
    for (int o = 128; o > 0; o >>= 1) {
        if (threadIdx.x < o) {
            float m2 = sm[threadIdx.x + o], s2 = ss[threadIdx.x + o];
            float M = fmaxf(sm[threadIdx.x], m2);
            ss[threadIdx.x] = ss[threadIdx.x] * __expf(sm[threadIdx.x] - M) + s2 * __expf(m2 - M);
            sm[threadIdx.x] = M;
        }
        __syncthreads();
    }
    const float lse = sm[0] + logf(ss[0]);
    for (int j = threadIdx.x; j < NOUT; j += 256) p[j] -= lse;
}

// ---------------- launcher ----------------
extern "C" void kernel_launch(void* const* d_in, const int* in_sizes, int n_in,
                              void* d_out, int out_size) {
    const float* x    = (const float*)d_in[0];
    const float* h0   = (const float*)d_in[1];
    const float* c0   = (const float*)d_in[2];
    const float* Wih0 = (const float*)d_in[3];
    const float* Whh0 = (const float*)d_in[4];
    const float* bih0 = (const float*)d_in[5];
    const float* bhh0 = (const float*)d_in[6];
    const float* Wih1 = (const float*)d_in[7];
    const float* Whh1 = (const float*)d_in[8];
    const float* bih1 = (const float*)d_in[9];
    const float* bhh1 = (const float*)d_in[10];
    const float* Wl   = (const float*)d_in[11];
    const float* bl   = (const float*)d_in[12];
    float* out = (float*)d_out;

    __nv_bfloat16 *wl, *hbb;
    float *G0, *G1, *ha, *hb; unsigned* bar;
    cudaGetSymbolAddress((void**)&wl,  g_Wlb);
    cudaGetSymbolAddress((void**)&G0,  g_G0);
    cudaGetSymbolAddress((void**)&G1,  g_G1);
    cudaGetSymbolAddress((void**)&ha,  g_ha);
    cudaGetSymbolAddress((void**)&hb,  g_hb);
    cudaGetSymbolAddress((void**)&hbb, g_hbb);
    cudaGetSymbolAddress((void**)&bar, g_bar);

    cudaFuncSetAttribute(lstm_pass, cudaFuncAttributeMaxDynamicSharedMemorySize, SMEM_LSTM);
    cudaFuncSetAttribute(gemm32_kernel, cudaFuncAttributeMaxDynamicSharedMemorySize, SMEM_G32);

    cudaMemsetAsync(bar, 0, 2 * sizeof(unsigned));

    f2bf_kernel<<<2048, 256>>>(Wl, wl, NOUT * NH);

    dim3 gG(G4 / 64, MROWS / 128);       // (64, 64)
    gemm32_kernel<<<gG, 256, SMEM_G32>>>(x, Wih0, bih0, bhh0, G0, MROWS, G4, NIN);

    lstm_pass<<<128, 256, SMEM_LSTM>>>(Whh0, G0, h0, c0, ha, nullptr,
                                       out + LOGP_ELEMS,
                                       out + LOGP_ELEMS + 2 * BATCH * NH, bar);

    gemm32_kernel<<<gG, 256, SMEM_G32>>>(ha, Wih1, bih1, bhh1, G1, MROWS, G4, NH);

    lstm_pass<<<128, 256, SMEM_LSTM>>>(Whh1, G1, h0 + BATCH * NH, c0 + BATCH * NH, hb, hbb,
                                       out + LOGP_ELEMS + BATCH * NH,
                                       out + LOGP_ELEMS + 3 * BATCH * NH, bar + 1);

    dim3 gH(NOUT / 128, MROWS / 128);    // (250, 64)
    gemm_kernel<<<gH, 256>>>(hbb, wl, bl, out, MROWS, NOUT, NH);

    logsoftmax_kernel<<<MROWS, 256>>>(out);
}